// round 5
// baseline (speedup 1.0000x reference)
#include <cuda_runtime.h>
#include <cuda_bf16.h>
#include <math.h>
#include <stdint.h>

#define T_SEQ 4096
#define D_MODEL 1024
#define N_HEAD 16
#define C_HEAD 64
#define QKV_W 3072

// Scratch (device globals: allocation-guard safe)
__device__ float g_qkv[(size_t)T_SEQ * QKV_W];     // [T][3D], q|k|v sections
__device__ float g_attn[(size_t)T_SEQ * D_MODEL];  // [T][D] attention output

// ---------------------------------------------------------------------------
// Split-bf16 tensor-core NT GEMM: C[m,n] = sum_k A[m,k] * B[n,k]
// fp32 in/out. Each fp32 value is split hi/lo into two bf16; product uses
// 3 MMAs (hi*hi + hi*lo + lo*hi), fp32 accumulate -> ~2^-17 effective error.
// Block 128x128, BK=32, 256 threads = 8 warps (2x4), warp tile 64x32,
// per warp: 4 m-tiles (16) x 4 n-tiles (8), mma.m16n8k8.
// ---------------------------------------------------------------------------
#define BMg 128
#define BNg 128
#define BKg 32

__device__ __forceinline__ void mma_bf16_16x8x8(float* c,
                                                uint32_t a0, uint32_t a1,
                                                uint32_t b0) {
    asm volatile(
        "mma.sync.aligned.m16n8k8.row.col.f32.bf16.bf16.f32 "
        "{%0,%1,%2,%3}, {%4,%5}, {%6}, {%0,%1,%2,%3};"
        : "+f"(c[0]), "+f"(c[1]), "+f"(c[2]), "+f"(c[3])
        : "r"(a0), "r"(a1), "r"(b0));
}

__global__ void gemm_nt_bf16x3_kernel(const float* __restrict__ A,
                                      const float* __restrict__ B,
                                      float* __restrict__ C,
                                      int M, int N, int K) {
    __shared__ __nv_bfloat16 Ah[BMg][BKg + 2];
    __shared__ __nv_bfloat16 Al[BMg][BKg + 2];
    __shared__ __nv_bfloat16 Bh[BNg][BKg + 2];
    __shared__ __nv_bfloat16 Bl[BNg][BKg + 2];

    int tid = threadIdx.x;
    int warp = tid >> 5;
    int lane = tid & 31;
    int wm = warp >> 2;          // 0..1
    int wn = warp & 3;           // 0..3
    int g = lane >> 2;           // groupID 0..7
    int tg = lane & 3;           // thread-in-group 0..3
    int m0 = blockIdx.y * BMg;
    int n0 = blockIdx.x * BNg;
    int wm0 = wm * 64;
    int wn0 = wn * 32;

    float acc[4][4][4] = {};     // [m-tile][n-tile][c-reg]

    for (int k0 = 0; k0 < K; k0 += BKg) {
        // Load + convert A and B tiles (128x32 fp32 each; 1024 float4 each).
#pragma unroll
        for (int i = 0; i < 4; i++) {
            int f = tid + i * 256;          // float4 index
            int r = f >> 3;                 // 8 float4 per row
            int c = (f & 7) * 4;
            float4 va = *(const float4*)(A + (size_t)(m0 + r) * K + k0 + c);
            float xs[4] = {va.x, va.y, va.z, va.w};
#pragma unroll
            for (int j = 0; j < 4; j++) {
                __nv_bfloat16 h = __float2bfloat16(xs[j]);
                Ah[r][c + j] = h;
                Al[r][c + j] = __float2bfloat16(xs[j] - __bfloat162float(h));
            }
            float4 vb = *(const float4*)(B + (size_t)(n0 + r) * K + k0 + c);
            float ys[4] = {vb.x, vb.y, vb.z, vb.w};
#pragma unroll
            for (int j = 0; j < 4; j++) {
                __nv_bfloat16 h = __float2bfloat16(ys[j]);
                Bh[r][c + j] = h;
                Bl[r][c + j] = __float2bfloat16(ys[j] - __bfloat162float(h));
            }
        }
        __syncthreads();

#pragma unroll
        for (int kc = 0; kc < BKg; kc += 8) {
            uint32_t ah[4][2], al[4][2], bh[4], bl[4];
#pragma unroll
            for (int mt = 0; mt < 4; mt++) {
                int r = wm0 + mt * 16 + g;
                ah[mt][0] = *(const uint32_t*)&Ah[r][kc + tg * 2];
                ah[mt][1] = *(const uint32_t*)&Ah[r + 8][kc + tg * 2];
                al[mt][0] = *(const uint32_t*)&Al[r][kc + tg * 2];
                al[mt][1] = *(const uint32_t*)&Al[r + 8][kc + tg * 2];
            }
#pragma unroll
            for (int nt = 0; nt < 4; nt++) {
                int r = wn0 + nt * 8 + g;
                bh[nt] = *(const uint32_t*)&Bh[r][kc + tg * 2];
                bl[nt] = *(const uint32_t*)&Bl[r][kc + tg * 2];
            }
#pragma unroll
            for (int mt = 0; mt < 4; mt++) {
#pragma unroll
                for (int nt = 0; nt < 4; nt++) {
                    mma_bf16_16x8x8(acc[mt][nt], ah[mt][0], ah[mt][1], bh[nt]);
                    mma_bf16_16x8x8(acc[mt][nt], ah[mt][0], ah[mt][1], bl[nt]);
                    mma_bf16_16x8x8(acc[mt][nt], al[mt][0], al[mt][1], bh[nt]);
                }
            }
        }
        __syncthreads();
    }

    // Epilogue: c0,c1 = (row g, cols tg*2, tg*2+1); c2,c3 = row g+8.
#pragma unroll
    for (int mt = 0; mt < 4; mt++) {
        int r = m0 + wm0 + mt * 16 + g;
#pragma unroll
        for (int nt = 0; nt < 4; nt++) {
            int cb = n0 + wn0 + nt * 8 + tg * 2;
            *(float2*)&C[(size_t)r * N + cb] =
                make_float2(acc[mt][nt][0], acc[mt][nt][1]);
            *(float2*)&C[(size_t)(r + 8) * N + cb] =
                make_float2(acc[mt][nt][2], acc[mt][nt][3]);
        }
    }
}

// ---------------------------------------------------------------------------
// RoPE in-place on q and k sections of g_qkv.
// ---------------------------------------------------------------------------
__global__ void rope_kernel(float* __restrict__ qkv) {
    int idx = blockIdx.x * blockDim.x + threadIdx.x;
    int pair = idx & 31;
    int h = (idx >> 5) & 15;
    int sec = (idx >> 9) & 1;       // 0 = q, 1 = k
    int t = idx >> 10;
    if (t >= T_SEQ) return;

    const float LOG_10000 = 9.210340371976184f;
    float expo = (2.f * (float)pair) / (float)C_HEAD;
    float inv_freq = expf(-expo * LOG_10000);
    float ang = (float)t * inv_freq;
    float s, c;
    sincosf(ang, &s, &c);

    size_t base = (size_t)t * QKV_W + sec * D_MODEL + h * C_HEAD + pair * 2;
    float x1 = qkv[base];
    float x2 = qkv[base + 1];
    qkv[base]     = x1 * c - x2 * s;
    qkv[base + 1] = x2 * c + x1 * s;
}

// ---------------------------------------------------------------------------
// Flash-attention (causal, online softmax). Unchanged from baseline.
// ---------------------------------------------------------------------------
#define ATTN_SMEM ((3 * 64 * 65 + 64 * 64 + 3 * 64) * sizeof(float))

__global__ void attn_kernel(const float* __restrict__ qkv,
                            float* __restrict__ out) {
    extern __shared__ float sm[];
    float* Qs = sm;                       // 64*65
    float* Ks = Qs + 64 * 65;             // 64*65
    float* Ss = Ks + 64 * 65;             // 64*65
    float* Vs = Ss + 64 * 65;             // 64*64
    float* row_m = Vs + 64 * 64;          // 64
    float* row_l = row_m + 64;            // 64
    float* row_c = row_l + 64;            // 64

    int tid = threadIdx.x;
    int tx = tid & 15;
    int ty = tid >> 4;
    int h = blockIdx.y;
    int t0 = (int)(gridDim.x - 1 - blockIdx.x) * 64;

    for (int l = tid; l < 1024; l += 256) {
        int r = l >> 4;
        int c = (l & 15) * 4;
        float4 v = *(const float4*)(qkv + (size_t)(t0 + r) * QKV_W + h * C_HEAD + c);
        Qs[r * 65 + c + 0] = v.x;
        Qs[r * 65 + c + 1] = v.y;
        Qs[r * 65 + c + 2] = v.z;
        Qs[r * 65 + c + 3] = v.w;
    }
    if (tid < 64) {
        row_m[tid] = -1e30f;
        row_l[tid] = 0.f;
    }

    float O[4][4];
#pragma unroll
    for (int i = 0; i < 4; i++)
#pragma unroll
        for (int j = 0; j < 4; j++) O[i][j] = 0.f;

    for (int s0 = 0; s0 <= t0; s0 += 64) {
        for (int l = tid; l < 1024; l += 256) {
            int r = l >> 4;
            int c = (l & 15) * 4;
            float4 v = *(const float4*)(qkv + (size_t)(s0 + r) * QKV_W + D_MODEL + h * C_HEAD + c);
            Ks[r * 65 + c + 0] = v.x;
            Ks[r * 65 + c + 1] = v.y;
            Ks[r * 65 + c + 2] = v.z;
            Ks[r * 65 + c + 3] = v.w;
        }
        __syncthreads();

        float s_acc[4][4];
#pragma unroll
        for (int i = 0; i < 4; i++)
#pragma unroll
            for (int j = 0; j < 4; j++) s_acc[i][j] = 0.f;

#pragma unroll
        for (int k = 0; k < 64; k++) {
            float a[4], b[4];
#pragma unroll
            for (int i = 0; i < 4; i++) a[i] = Qs[(ty * 4 + i) * 65 + k];
#pragma unroll
            for (int j = 0; j < 4; j++) b[j] = Ks[(tx * 4 + j) * 65 + k];
#pragma unroll
            for (int i = 0; i < 4; i++)
#pragma unroll
                for (int j = 0; j < 4; j++) s_acc[i][j] += a[i] * b[j];
        }

        bool diag = (s0 == t0);
#pragma unroll
        for (int i = 0; i < 4; i++) {
#pragma unroll
            for (int j = 0; j < 4; j++) {
                float sv = s_acc[i][j] * 0.125f;
                if (diag && (tx * 4 + j) > (ty * 4 + i)) sv = -1e30f;
                Ss[(ty * 4 + i) * 65 + tx * 4 + j] = sv;
            }
        }

        for (int l = tid; l < 1024; l += 256) {
            int r = l >> 4;
            int c = (l & 15) * 4;
            float4 v = *(const float4*)(qkv + (size_t)(s0 + r) * QKV_W + 2 * D_MODEL + h * C_HEAD + c);
            *(float4*)(Vs + r * 64 + c) = v;
        }
        __syncthreads();

        if (tid < 64) {
            int r = tid;
            float mo = row_m[r];
            float mx = mo;
#pragma unroll 8
            for (int s = 0; s < 64; s++) mx = fmaxf(mx, Ss[r * 65 + s]);
            float corr = __expf(mo - mx);
            float sum = 0.f;
#pragma unroll 8
            for (int s = 0; s < 64; s++) {
                float p = __expf(Ss[r * 65 + s] - mx);
                Ss[r * 65 + s] = p;
                sum += p;
            }
            row_l[r] = row_l[r] * corr + sum;
            row_m[r] = mx;
            row_c[r] = corr;
        }
        __syncthreads();

        float corr[4];
#pragma unroll
        for (int i = 0; i < 4; i++) corr[i] = row_c[ty * 4 + i];
#pragma unroll
        for (int i = 0; i < 4; i++)
#pragma unroll
            for (int j = 0; j < 4; j++) O[i][j] *= corr[i];

#pragma unroll
        for (int k = 0; k < 64; k++) {
            float a[4], b[4];
#pragma unroll
            for (int i = 0; i < 4; i++) a[i] = Ss[(ty * 4 + i) * 65 + k];
#pragma unroll
            for (int j = 0; j < 4; j++) b[j] = Vs[k * 64 + tx * 4 + j];
#pragma unroll
            for (int i = 0; i < 4; i++)
#pragma unroll
                for (int j = 0; j < 4; j++) O[i][j] += a[i] * b[j];
        }
    }

#pragma unroll
    for (int i = 0; i < 4; i++) {
        int t = t0 + ty * 4 + i;
        float inv = 1.f / row_l[ty * 4 + i];
#pragma unroll
        for (int j = 0; j < 4; j++) {
            out[(size_t)t * D_MODEL + h * C_HEAD + tx * 4 + j] = O[i][j] * inv;
        }
    }
}

// ---------------------------------------------------------------------------
extern "C" void kernel_launch(void* const* d_in, const int* in_sizes, int n_in,
                              void* d_out, int out_size) {
    const float* x      = (const float*)d_in[0];   // [4096,1024]
    const float* W_qkv  = (const float*)d_in[1];   // [3072,1024]
    const float* W_proj = (const float*)d_in[2];   // [1024,1024]
    float* out = (float*)d_out;                    // [4096,1024]

    float* qkv_ptr;
    float* attn_ptr;
    cudaGetSymbolAddress((void**)&qkv_ptr, g_qkv);
    cudaGetSymbolAddress((void**)&attn_ptr, g_attn);

    cudaFuncSetAttribute(attn_kernel, cudaFuncAttributeMaxDynamicSharedMemorySize,
                         (int)ATTN_SMEM);

    // 1) qkv = x @ W_qkv^T   (tensor-core split-bf16)
    {
        dim3 grid(QKV_W / BNg, T_SEQ / BMg);
        gemm_nt_bf16x3_kernel<<<grid, 256>>>(x, W_qkv, qkv_ptr, T_SEQ, QKV_W, D_MODEL);
    }

    // 2) RoPE on q,k in place
    {
        int total = T_SEQ * 2 * N_HEAD * (C_HEAD / 2);  // 4194304
        rope_kernel<<<total / 256, 256>>>(qkv_ptr);
    }

    // 3) causal attention
    {
        dim3 grid(T_SEQ / 64, N_HEAD);
        attn_kernel<<<grid, 256, ATTN_SMEM>>>(qkv_ptr, attn_ptr);
    }

    // 4) out = attn @ W_proj^T   (tensor-core split-bf16)
    {
        dim3 grid(D_MODEL / BNg, T_SEQ / BMg);
        gemm_nt_bf16x3_kernel<<<grid, 256>>>(attn_ptr, W_proj, out, T_SEQ, D_MODEL, D_MODEL);
    }
}

// round 6
// speedup vs baseline: 1.6774x; 1.6774x over previous
#include <cuda_runtime.h>
#include <cuda_bf16.h>
#include <math.h>
#include <stdint.h>

#define T_SEQ 4096
#define D_MODEL 1024
#define N_HEAD 16
#define C_HEAD 64
#define QKV_W 3072

// Scratch (device globals: allocation-guard safe)
__device__ float g_qkv[(size_t)T_SEQ * QKV_W];     // [T][3D], q|k|v sections
__device__ float g_attn[(size_t)T_SEQ * D_MODEL];  // [T][D] attention output

// ---------------------------------------------------------------------------
// Common helpers
// ---------------------------------------------------------------------------
__device__ __forceinline__ uint32_t smem_u32(const void* p) {
    return (uint32_t)__cvta_generic_to_shared(p);
}

__device__ __forceinline__ uint32_t pack_bf16(float x, float y) {
    __nv_bfloat162 t = __floats2bfloat162_rn(x, y);   // .x = x in low 16 bits
    return *(uint32_t*)&t;
}

__device__ __forceinline__ void mma_bf16_16x8x8(float* c,
                                                uint32_t a0, uint32_t a1,
                                                uint32_t b0) {
    asm volatile(
        "mma.sync.aligned.m16n8k8.row.col.f32.bf16.bf16.f32 "
        "{%0,%1,%2,%3}, {%4,%5}, {%6}, {%0,%1,%2,%3};"
        : "+f"(c[0]), "+f"(c[1]), "+f"(c[2]), "+f"(c[3])
        : "r"(a0), "r"(a1), "r"(b0));
}

__device__ __forceinline__ void mma_bf16_16x8x16(float* c, const uint32_t* a,
                                                 uint32_t b0, uint32_t b1) {
    asm volatile(
        "mma.sync.aligned.m16n8k16.row.col.f32.bf16.bf16.f32 "
        "{%0,%1,%2,%3}, {%4,%5,%6,%7}, {%8,%9}, {%0,%1,%2,%3};"
        : "+f"(c[0]), "+f"(c[1]), "+f"(c[2]), "+f"(c[3])
        : "r"(a[0]), "r"(a[1]), "r"(a[2]), "r"(a[3]), "r"(b0), "r"(b1));
}

__device__ __forceinline__ void ldm_x2(uint32_t& r0, uint32_t& r1, uint32_t addr) {
    asm volatile("ldmatrix.sync.aligned.m8n8.x2.shared.b16 {%0,%1}, [%2];"
                 : "=r"(r0), "=r"(r1) : "r"(addr));
}

__device__ __forceinline__ void ldm_x2_trans(uint32_t& r0, uint32_t& r1, uint32_t addr) {
    asm volatile("ldmatrix.sync.aligned.m8n8.x2.trans.shared.b16 {%0,%1}, [%2];"
                 : "=r"(r0), "=r"(r1) : "r"(addr));
}

// ---------------------------------------------------------------------------
// Split-bf16 tensor-core NT GEMM (unchanged from passing R5 kernel)
// ---------------------------------------------------------------------------
#define BMg 128
#define BNg 128
#define BKg 32

__global__ void gemm_nt_bf16x3_kernel(const float* __restrict__ A,
                                      const float* __restrict__ B,
                                      float* __restrict__ C,
                                      int M, int N, int K) {
    __shared__ __nv_bfloat16 Ah[BMg][BKg + 2];
    __shared__ __nv_bfloat16 Al[BMg][BKg + 2];
    __shared__ __nv_bfloat16 Bh[BNg][BKg + 2];
    __shared__ __nv_bfloat16 Bl[BNg][BKg + 2];

    int tid = threadIdx.x;
    int warp = tid >> 5;
    int lane = tid & 31;
    int wm = warp >> 2;
    int wn = warp & 3;
    int g = lane >> 2;
    int tg = lane & 3;
    int m0 = blockIdx.y * BMg;
    int n0 = blockIdx.x * BNg;
    int wm0 = wm * 64;
    int wn0 = wn * 32;

    float acc[4][4][4] = {};

    for (int k0 = 0; k0 < K; k0 += BKg) {
#pragma unroll
        for (int i = 0; i < 4; i++) {
            int f = tid + i * 256;
            int r = f >> 3;
            int c = (f & 7) * 4;
            float4 va = *(const float4*)(A + (size_t)(m0 + r) * K + k0 + c);
            float xs[4] = {va.x, va.y, va.z, va.w};
#pragma unroll
            for (int j = 0; j < 4; j++) {
                __nv_bfloat16 hh = __float2bfloat16(xs[j]);
                Ah[r][c + j] = hh;
                Al[r][c + j] = __float2bfloat16(xs[j] - __bfloat162float(hh));
            }
            float4 vb = *(const float4*)(B + (size_t)(n0 + r) * K + k0 + c);
            float ys[4] = {vb.x, vb.y, vb.z, vb.w};
#pragma unroll
            for (int j = 0; j < 4; j++) {
                __nv_bfloat16 hh = __float2bfloat16(ys[j]);
                Bh[r][c + j] = hh;
                Bl[r][c + j] = __float2bfloat16(ys[j] - __bfloat162float(hh));
            }
        }
        __syncthreads();

#pragma unroll
        for (int kc = 0; kc < BKg; kc += 8) {
            uint32_t ah[4][2], al[4][2], bh[4], bl[4];
#pragma unroll
            for (int mt = 0; mt < 4; mt++) {
                int r = wm0 + mt * 16 + g;
                ah[mt][0] = *(const uint32_t*)&Ah[r][kc + tg * 2];
                ah[mt][1] = *(const uint32_t*)&Ah[r + 8][kc + tg * 2];
                al[mt][0] = *(const uint32_t*)&Al[r][kc + tg * 2];
                al[mt][1] = *(const uint32_t*)&Al[r + 8][kc + tg * 2];
            }
#pragma unroll
            for (int nt = 0; nt < 4; nt++) {
                int r = wn0 + nt * 8 + g;
                bh[nt] = *(const uint32_t*)&Bh[r][kc + tg * 2];
                bl[nt] = *(const uint32_t*)&Bl[r][kc + tg * 2];
            }
#pragma unroll
            for (int mt = 0; mt < 4; mt++) {
#pragma unroll
                for (int nt = 0; nt < 4; nt++) {
                    mma_bf16_16x8x8(acc[mt][nt], ah[mt][0], ah[mt][1], bh[nt]);
                    mma_bf16_16x8x8(acc[mt][nt], ah[mt][0], ah[mt][1], bl[nt]);
                    mma_bf16_16x8x8(acc[mt][nt], al[mt][0], al[mt][1], bh[nt]);
                }
            }
        }
        __syncthreads();
    }

#pragma unroll
    for (int mt = 0; mt < 4; mt++) {
        int r = m0 + wm0 + mt * 16 + g;
#pragma unroll
        for (int nt = 0; nt < 4; nt++) {
            int cb = n0 + wn0 + nt * 8 + tg * 2;
            *(float2*)&C[(size_t)r * N + cb] =
                make_float2(acc[mt][nt][0], acc[mt][nt][1]);
            *(float2*)&C[(size_t)(r + 8) * N + cb] =
                make_float2(acc[mt][nt][2], acc[mt][nt][3]);
        }
    }
}

// ---------------------------------------------------------------------------
// RoPE in-place on q and k sections of g_qkv (unchanged).
// ---------------------------------------------------------------------------
__global__ void rope_kernel(float* __restrict__ qkv) {
    int idx = blockIdx.x * blockDim.x + threadIdx.x;
    int pair = idx & 31;
    int h = (idx >> 5) & 15;
    int sec = (idx >> 9) & 1;
    int t = idx >> 10;
    if (t >= T_SEQ) return;

    const float LOG_10000 = 9.210340371976184f;
    float expo = (2.f * (float)pair) / (float)C_HEAD;
    float inv_freq = expf(-expo * LOG_10000);
    float ang = (float)t * inv_freq;
    float s, c;
    sincosf(ang, &s, &c);

    size_t base = (size_t)t * QKV_W + sec * D_MODEL + h * C_HEAD + pair * 2;
    float x1 = qkv[base];
    float x2 = qkv[base + 1];
    qkv[base]     = x1 * c - x2 * s;
    qkv[base + 1] = x2 * c + x1 * s;
}

// ---------------------------------------------------------------------------
// Tensor-core flash attention (causal, FA2-style register softmax).
// Grid (T/64, H), 128 threads = 4 warps. Br=64 (16 rows/warp), Bc=64, C=64.
// Split hi/lo bf16 3-MMA for both Q@K^T and P@V.
// ---------------------------------------------------------------------------
__global__ void __launch_bounds__(128)
attn_mma_kernel(const float* __restrict__ qkv, float* __restrict__ out) {
    __shared__ __nv_bfloat16 KsH[64][72];
    __shared__ __nv_bfloat16 KsL[64][72];
    __shared__ __nv_bfloat16 VsH[64][72];
    __shared__ __nv_bfloat16 VsL[64][72];

    int tid = threadIdx.x;
    int lane = tid & 31;
    int warp = tid >> 5;
    int g = lane >> 2;
    int tg = lane & 3;
    int li = lane & 15;
    int h = blockIdx.y;
    int t0 = (int)(gridDim.x - 1 - blockIdx.x) * 64;   // big workloads first
    int wrow = warp * 16;
    int rg = t0 + wrow + g;       // row for c0/c1 (and a0/a2)
    int rg8 = rg + 8;             // row for c2/c3 (and a1/a3)

    // --- Q fragments (pre-scaled by 1/sqrt(64)), hi/lo split, in registers ---
    uint32_t qh[4][4], ql[4][4];
#pragma unroll
    for (int ks = 0; ks < 4; ks++) {
        int c0 = h * C_HEAD + ks * 16 + 2 * tg;
#pragma unroll
        for (int ai = 0; ai < 4; ai++) {
            int r = (ai & 1) ? rg8 : rg;
            int c = c0 + ((ai & 2) ? 8 : 0);
            float2 v = *(const float2*)(qkv + (size_t)r * QKV_W + c);
            float x = v.x * 0.125f, y = v.y * 0.125f;
            __nv_bfloat16 hx = __float2bfloat16(x), hy = __float2bfloat16(y);
            qh[ks][ai] = pack_bf16(__bfloat162float(hx), __bfloat162float(hy));
            ql[ks][ai] = pack_bf16(x - __bfloat162float(hx),
                                   y - __bfloat162float(hy));
        }
    }

    // ldmatrix base addresses (per thread)
    uint32_t baseKH = smem_u32(&KsH[li & 7][(li & 8) ? 8 : 0]);
    uint32_t baseKL = smem_u32(&KsL[li & 7][(li & 8) ? 8 : 0]);
    uint32_t baseVH = smem_u32(&VsH[li][0]);
    uint32_t baseVL = smem_u32(&VsL[li][0]);

    float O[8][4];
#pragma unroll
    for (int nt = 0; nt < 8; nt++)
#pragma unroll
        for (int j = 0; j < 4; j++) O[nt][j] = 0.f;
    float m0r = -1e30f, m1r = -1e30f, l0r = 0.f, l1r = 0.f;

    for (int s0 = 0; s0 <= t0; s0 += 64) {
        __syncthreads();   // previous tile's reads done before overwrite

        // --- Load K,V tiles: global fp32 -> hi/lo bf16 smem ---
#pragma unroll
        for (int i = 0; i < 8; i++) {
            int f = tid + i * 128;        // 0..1023 float4 slots
            int key = f >> 4;
            int d4 = (f & 15) * 4;
            const float* kp = qkv + (size_t)(s0 + key) * QKV_W + D_MODEL + h * C_HEAD + d4;
            float4 kv = *(const float4*)kp;
            float ka[4] = {kv.x, kv.y, kv.z, kv.w};
#pragma unroll
            for (int j = 0; j < 4; j++) {
                __nv_bfloat16 hh = __float2bfloat16(ka[j]);
                KsH[key][d4 + j] = hh;
                KsL[key][d4 + j] = __float2bfloat16(ka[j] - __bfloat162float(hh));
            }
            const float* vp = qkv + (size_t)(s0 + key) * QKV_W + 2 * D_MODEL + h * C_HEAD + d4;
            float4 vv = *(const float4*)vp;
            float va[4] = {vv.x, vv.y, vv.z, vv.w};
#pragma unroll
            for (int j = 0; j < 4; j++) {
                __nv_bfloat16 hh = __float2bfloat16(va[j]);
                VsH[key][d4 + j] = hh;
                VsL[key][d4 + j] = __float2bfloat16(va[j] - __bfloat162float(hh));
            }
        }
        __syncthreads();

        // --- S = (Q/8) @ K^T : c-frags sc[8][4] ---
        float sc[8][4];
#pragma unroll
        for (int nt = 0; nt < 8; nt++)
#pragma unroll
            for (int j = 0; j < 4; j++) sc[nt][j] = 0.f;

#pragma unroll
        for (int ks = 0; ks < 4; ks++) {
#pragma unroll
            for (int nt = 0; nt < 8; nt++) {
                uint32_t off = (uint32_t)((nt * 8 * 72 + ks * 16) * 2);
                uint32_t bh0, bh1, bl0, bl1;
                ldm_x2(bh0, bh1, baseKH + off);
                ldm_x2(bl0, bl1, baseKL + off);
                mma_bf16_16x8x16(sc[nt], qh[ks], bh0, bh1);
                mma_bf16_16x8x16(sc[nt], qh[ks], bl0, bl1);
                mma_bf16_16x8x16(sc[nt], ql[ks], bh0, bh1);
            }
        }

        // --- causal mask (only the diagonal tile) ---
        if (s0 == t0) {
#pragma unroll
            for (int nt = 0; nt < 8; nt++) {
                int col = s0 + nt * 8 + 2 * tg;
                if (col > rg)      sc[nt][0] = -1e30f;
                if (col + 1 > rg)  sc[nt][1] = -1e30f;
                if (col > rg8)     sc[nt][2] = -1e30f;
                if (col + 1 > rg8) sc[nt][3] = -1e30f;
            }
        }

        // --- online softmax (rows g and g+8) ---
        float mx0 = m0r, mx1 = m1r;
#pragma unroll
        for (int nt = 0; nt < 8; nt++) {
            mx0 = fmaxf(mx0, fmaxf(sc[nt][0], sc[nt][1]));
            mx1 = fmaxf(mx1, fmaxf(sc[nt][2], sc[nt][3]));
        }
        mx0 = fmaxf(mx0, __shfl_xor_sync(0xffffffffu, mx0, 1));
        mx0 = fmaxf(mx0, __shfl_xor_sync(0xffffffffu, mx0, 2));
        mx1 = fmaxf(mx1, __shfl_xor_sync(0xffffffffu, mx1, 1));
        mx1 = fmaxf(mx1, __shfl_xor_sync(0xffffffffu, mx1, 2));

        float sum0 = 0.f, sum1 = 0.f;
#pragma unroll
        for (int nt = 0; nt < 8; nt++) {
            sc[nt][0] = __expf(sc[nt][0] - mx0);
            sc[nt][1] = __expf(sc[nt][1] - mx0);
            sc[nt][2] = __expf(sc[nt][2] - mx1);
            sc[nt][3] = __expf(sc[nt][3] - mx1);
            sum0 += sc[nt][0] + sc[nt][1];
            sum1 += sc[nt][2] + sc[nt][3];
        }
        sum0 += __shfl_xor_sync(0xffffffffu, sum0, 1);
        sum0 += __shfl_xor_sync(0xffffffffu, sum0, 2);
        sum1 += __shfl_xor_sync(0xffffffffu, sum1, 1);
        sum1 += __shfl_xor_sync(0xffffffffu, sum1, 2);

        float corr0 = __expf(m0r - mx0);
        float corr1 = __expf(m1r - mx1);
        l0r = l0r * corr0 + sum0;
        l1r = l1r * corr1 + sum1;
        m0r = mx0;
        m1r = mx1;
#pragma unroll
        for (int nt = 0; nt < 8; nt++) {
            O[nt][0] *= corr0;
            O[nt][1] *= corr0;
            O[nt][2] *= corr1;
            O[nt][3] *= corr1;
        }

        // --- P fragments (hi/lo), A-frag layout from C-frag layout ---
        uint32_t ph[4][4], pl[4][4];
#pragma unroll
        for (int ks = 0; ks < 4; ks++) {
#pragma unroll
            for (int half = 0; half < 2; half++) {     // ntile 2ks, 2ks+1
                int nt = 2 * ks + half;
                float p0 = sc[nt][0], p1 = sc[nt][1];
                float p2 = sc[nt][2], p3 = sc[nt][3];
                __nv_bfloat16 h0 = __float2bfloat16(p0), h1 = __float2bfloat16(p1);
                __nv_bfloat16 h2 = __float2bfloat16(p2), h3 = __float2bfloat16(p3);
                ph[ks][0 + 2 * half] = pack_bf16(__bfloat162float(h0), __bfloat162float(h1));
                ph[ks][1 + 2 * half] = pack_bf16(__bfloat162float(h2), __bfloat162float(h3));
                pl[ks][0 + 2 * half] = pack_bf16(p0 - __bfloat162float(h0),
                                                 p1 - __bfloat162float(h1));
                pl[ks][1 + 2 * half] = pack_bf16(p2 - __bfloat162float(h2),
                                                 p3 - __bfloat162float(h3));
            }
        }

        // --- O += P @ V ---
#pragma unroll
        for (int ks = 0; ks < 4; ks++) {
#pragma unroll
            for (int nt = 0; nt < 8; nt++) {
                uint32_t off = (uint32_t)((ks * 16 * 72 + nt * 8) * 2);
                uint32_t bh0, bh1, bl0, bl1;
                ldm_x2_trans(bh0, bh1, baseVH + off);
                ldm_x2_trans(bl0, bl1, baseVL + off);
                mma_bf16_16x8x16(O[nt], ph[ks], bh0, bh1);
                mma_bf16_16x8x16(O[nt], ph[ks], bl0, bl1);
                mma_bf16_16x8x16(O[nt], pl[ks], bh0, bh1);
            }
        }
    }

    // --- normalize + write ---
    float inv0 = 1.f / l0r;
    float inv1 = 1.f / l1r;
#pragma unroll
    for (int nt = 0; nt < 8; nt++) {
        int cb = h * C_HEAD + nt * 8 + 2 * tg;
        *(float2*)&out[(size_t)rg * D_MODEL + cb] =
            make_float2(O[nt][0] * inv0, O[nt][1] * inv0);
        *(float2*)&out[(size_t)rg8 * D_MODEL + cb] =
            make_float2(O[nt][2] * inv1, O[nt][3] * inv1);
    }
}

// ---------------------------------------------------------------------------
extern "C" void kernel_launch(void* const* d_in, const int* in_sizes, int n_in,
                              void* d_out, int out_size) {
    const float* x      = (const float*)d_in[0];   // [4096,1024]
    const float* W_qkv  = (const float*)d_in[1];   // [3072,1024]
    const float* W_proj = (const float*)d_in[2];   // [1024,1024]
    float* out = (float*)d_out;                    // [4096,1024]

    float* qkv_ptr;
    float* attn_ptr;
    cudaGetSymbolAddress((void**)&qkv_ptr, g_qkv);
    cudaGetSymbolAddress((void**)&attn_ptr, g_attn);

    // 1) qkv = x @ W_qkv^T   (tensor-core split-bf16)
    {
        dim3 grid(QKV_W / BNg, T_SEQ / BMg);
        gemm_nt_bf16x3_kernel<<<grid, 256>>>(x, W_qkv, qkv_ptr, T_SEQ, QKV_W, D_MODEL);
    }

    // 2) RoPE on q,k in place
    {
        int total = T_SEQ * 2 * N_HEAD * (C_HEAD / 2);  // 4194304
        rope_kernel<<<total / 256, 256>>>(qkv_ptr);
    }

    // 3) causal attention (tensor-core)
    {
        dim3 grid(T_SEQ / 64, N_HEAD);
        attn_mma_kernel<<<grid, 128>>>(qkv_ptr, attn_ptr);
    }

    // 4) out = attn @ W_proj^T   (tensor-core split-bf16)
    {
        dim3 grid(D_MODEL / BNg, T_SEQ / BMg);
        gemm_nt_bf16x3_kernel<<<grid, 256>>>(attn_ptr, W_proj, out, T_SEQ, D_MODEL, D_MODEL);
    }
}

// round 9
// speedup vs baseline: 1.7826x; 1.0627x over previous
#include <cuda_runtime.h>
#include <cuda_bf16.h>
#include <math.h>
#include <stdint.h>

#define T_SEQ 4096
#define D_MODEL 1024
#define N_HEAD 16
#define C_HEAD 64
#define QKV_W 3072

// Scratch (device globals: allocation-guard safe)
__device__ float g_qkv[(size_t)T_SEQ * QKV_W];     // [T][3D], q|k|v sections
__device__ float g_attn[(size_t)T_SEQ * D_MODEL];  // [T][D] attention output
// Precomputed hi/lo bf16 (RoPE'd; Q pre-scaled by 1/8)
__device__ __nv_bfloat16 g_qh[(size_t)T_SEQ * D_MODEL];
__device__ __nv_bfloat16 g_ql[(size_t)T_SEQ * D_MODEL];
__device__ __nv_bfloat16 g_kh[(size_t)T_SEQ * D_MODEL];
__device__ __nv_bfloat16 g_kl[(size_t)T_SEQ * D_MODEL];
__device__ __nv_bfloat16 g_vh[(size_t)T_SEQ * D_MODEL];
__device__ __nv_bfloat16 g_vl[(size_t)T_SEQ * D_MODEL];

// ---------------------------------------------------------------------------
// Common helpers
// ---------------------------------------------------------------------------
__device__ __forceinline__ uint32_t smem_u32(const void* p) {
    return (uint32_t)__cvta_generic_to_shared(p);
}

__device__ __forceinline__ uint32_t pack_bf16(float x, float y) {
    __nv_bfloat162 t = __floats2bfloat162_rn(x, y);
    return *(uint32_t*)&t;
}

__device__ __forceinline__ void mma_bf16_16x8x8(float* c,
                                                uint32_t a0, uint32_t a1,
                                                uint32_t b0) {
    asm volatile(
        "mma.sync.aligned.m16n8k8.row.col.f32.bf16.bf16.f32 "
        "{%0,%1,%2,%3}, {%4,%5}, {%6}, {%0,%1,%2,%3};"
        : "+f"(c[0]), "+f"(c[1]), "+f"(c[2]), "+f"(c[3])
        : "r"(a0), "r"(a1), "r"(b0));
}

__device__ __forceinline__ void mma_bf16_16x8x16(float* c, const uint32_t* a,
                                                 uint32_t b0, uint32_t b1) {
    asm volatile(
        "mma.sync.aligned.m16n8k16.row.col.f32.bf16.bf16.f32 "
        "{%0,%1,%2,%3}, {%4,%5,%6,%7}, {%8,%9}, {%0,%1,%2,%3};"
        : "+f"(c[0]), "+f"(c[1]), "+f"(c[2]), "+f"(c[3])
        : "r"(a[0]), "r"(a[1]), "r"(a[2]), "r"(a[3]), "r"(b0), "r"(b1));
}

__device__ __forceinline__ void ldm_x2(uint32_t& r0, uint32_t& r1, uint32_t addr) {
    asm volatile("ldmatrix.sync.aligned.m8n8.x2.shared.b16 {%0,%1}, [%2];"
                 : "=r"(r0), "=r"(r1) : "r"(addr));
}

__device__ __forceinline__ void ldm_x2_trans(uint32_t& r0, uint32_t& r1, uint32_t addr) {
    asm volatile("ldmatrix.sync.aligned.m8n8.x2.trans.shared.b16 {%0,%1}, [%2];"
                 : "=r"(r0), "=r"(r1) : "r"(addr));
}

__device__ __forceinline__ void cpa16(uint32_t dst, const __nv_bfloat16* src) {
    asm volatile("cp.async.cg.shared.global [%0], [%1], 16;"
                 :: "r"(dst), "l"(__cvta_generic_to_global(src)));
}
__device__ __forceinline__ void cpa_commit() {
    asm volatile("cp.async.commit_group;");
}
template <int N>
__device__ __forceinline__ void cpa_wait() {
    asm volatile("cp.async.wait_group %0;" :: "n"(N));
}

// ---------------------------------------------------------------------------
// Split-bf16 tensor-core NT GEMM (unchanged from passing R5/R6 kernel)
// ---------------------------------------------------------------------------
#define BMg 128
#define BNg 128
#define BKg 32

__global__ void gemm_nt_bf16x3_kernel(const float* __restrict__ A,
                                      const float* __restrict__ B,
                                      float* __restrict__ C,
                                      int M, int N, int K) {
    __shared__ __nv_bfloat16 Ah[BMg][BKg + 2];
    __shared__ __nv_bfloat16 Al[BMg][BKg + 2];
    __shared__ __nv_bfloat16 Bh[BNg][BKg + 2];
    __shared__ __nv_bfloat16 Bl[BNg][BKg + 2];

    int tid = threadIdx.x;
    int warp = tid >> 5;
    int lane = tid & 31;
    int wm = warp >> 2;
    int wn = warp & 3;
    int g = lane >> 2;
    int tg = lane & 3;
    int m0 = blockIdx.y * BMg;
    int n0 = blockIdx.x * BNg;
    int wm0 = wm * 64;
    int wn0 = wn * 32;

    float acc[4][4][4] = {};

    for (int k0 = 0; k0 < K; k0 += BKg) {
#pragma unroll
        for (int i = 0; i < 4; i++) {
            int f = tid + i * 256;
            int r = f >> 3;
            int c = (f & 7) * 4;
            float4 va = *(const float4*)(A + (size_t)(m0 + r) * K + k0 + c);
            float xs[4] = {va.x, va.y, va.z, va.w};
#pragma unroll
            for (int j = 0; j < 4; j++) {
                __nv_bfloat16 hh = __float2bfloat16(xs[j]);
                Ah[r][c + j] = hh;
                Al[r][c + j] = __float2bfloat16(xs[j] - __bfloat162float(hh));
            }
            float4 vb = *(const float4*)(B + (size_t)(n0 + r) * K + k0 + c);
            float ys[4] = {vb.x, vb.y, vb.z, vb.w};
#pragma unroll
            for (int j = 0; j < 4; j++) {
                __nv_bfloat16 hh = __float2bfloat16(ys[j]);
                Bh[r][c + j] = hh;
                Bl[r][c + j] = __float2bfloat16(ys[j] - __bfloat162float(hh));
            }
        }
        __syncthreads();

#pragma unroll
        for (int kc = 0; kc < BKg; kc += 8) {
            uint32_t ah[4][2], al[4][2], bh[4], bl[4];
#pragma unroll
            for (int mt = 0; mt < 4; mt++) {
                int r = wm0 + mt * 16 + g;
                ah[mt][0] = *(const uint32_t*)&Ah[r][kc + tg * 2];
                ah[mt][1] = *(const uint32_t*)&Ah[r + 8][kc + tg * 2];
                al[mt][0] = *(const uint32_t*)&Al[r][kc + tg * 2];
                al[mt][1] = *(const uint32_t*)&Al[r + 8][kc + tg * 2];
            }
#pragma unroll
            for (int nt = 0; nt < 4; nt++) {
                int r = wn0 + nt * 8 + g;
                bh[nt] = *(const uint32_t*)&Bh[r][kc + tg * 2];
                bl[nt] = *(const uint32_t*)&Bl[r][kc + tg * 2];
            }
#pragma unroll
            for (int mt = 0; mt < 4; mt++) {
#pragma unroll
                for (int nt = 0; nt < 4; nt++) {
                    mma_bf16_16x8x8(acc[mt][nt], ah[mt][0], ah[mt][1], bh[nt]);
                    mma_bf16_16x8x8(acc[mt][nt], ah[mt][0], ah[mt][1], bl[nt]);
                    mma_bf16_16x8x8(acc[mt][nt], al[mt][0], al[mt][1], bh[nt]);
                }
            }
        }
        __syncthreads();
    }

#pragma unroll
    for (int mt = 0; mt < 4; mt++) {
        int r = m0 + wm0 + mt * 16 + g;
#pragma unroll
        for (int nt = 0; nt < 4; nt++) {
            int cb = n0 + wn0 + nt * 8 + tg * 2;
            *(float2*)&C[(size_t)r * N + cb] =
                make_float2(acc[mt][nt][0], acc[mt][nt][1]);
            *(float2*)&C[(size_t)(r + 8) * N + cb] =
                make_float2(acc[mt][nt][2], acc[mt][nt][3]);
        }
    }
}

// ---------------------------------------------------------------------------
// Fused RoPE + hi/lo bf16 conversion. One thread per (t, head, pair).
// q: rope, *0.125, split.  k: rope, split.  v: split.
// ---------------------------------------------------------------------------
__global__ void rope_convert_kernel(const float* __restrict__ qkv) {
    int idx = blockIdx.x * blockDim.x + threadIdx.x;   // 0 .. T*512-1
    int p = idx & 31;                // pair index within head
    int h = (idx >> 5) & 15;
    int t = idx >> 9;
    if (t >= T_SEQ) return;

    const float LOG_10000 = 9.210340371976184f;
    float inv_freq = expf(-(2.f * (float)p / (float)C_HEAD) * LOG_10000);
    float ang = (float)t * inv_freq;
    float s, c;
    sincosf(ang, &s, &c);

    int d = h * C_HEAD + 2 * p;
    size_t qbase = (size_t)t * QKV_W + d;
    size_t obase = (size_t)t * D_MODEL + d;

    // q: rope + scale + split
    {
        float x1 = qkv[qbase], x2 = qkv[qbase + 1];
        float r1 = (x1 * c - x2 * s) * 0.125f;
        float r2 = (x2 * c + x1 * s) * 0.125f;
        __nv_bfloat16 h1 = __float2bfloat16(r1), h2 = __float2bfloat16(r2);
        *(__nv_bfloat162*)&g_qh[obase] = __nv_bfloat162(h1, h2);
        *(__nv_bfloat162*)&g_ql[obase] = __nv_bfloat162(
            __float2bfloat16(r1 - __bfloat162float(h1)),
            __float2bfloat16(r2 - __bfloat162float(h2)));
    }
    // k: rope + split
    {
        float x1 = qkv[qbase + D_MODEL], x2 = qkv[qbase + D_MODEL + 1];
        float r1 = x1 * c - x2 * s;
        float r2 = x2 * c + x1 * s;
        __nv_bfloat16 h1 = __float2bfloat16(r1), h2 = __float2bfloat16(r2);
        *(__nv_bfloat162*)&g_kh[obase] = __nv_bfloat162(h1, h2);
        *(__nv_bfloat162*)&g_kl[obase] = __nv_bfloat162(
            __float2bfloat16(r1 - __bfloat162float(h1)),
            __float2bfloat16(r2 - __bfloat162float(h2)));
    }
    // v: split
    {
        float x1 = qkv[qbase + 2 * D_MODEL], x2 = qkv[qbase + 2 * D_MODEL + 1];
        __nv_bfloat16 h1 = __float2bfloat16(x1), h2 = __float2bfloat16(x2);
        *(__nv_bfloat162*)&g_vh[obase] = __nv_bfloat162(h1, h2);
        *(__nv_bfloat162*)&g_vl[obase] = __nv_bfloat162(
            __float2bfloat16(x1 - __bfloat162float(h1)),
            __float2bfloat16(x2 - __bfloat162float(h2)));
    }
}

// ---------------------------------------------------------------------------
// Tensor-core flash attention, Br=128, Bc=64, 256 threads (8 warps),
// cp.async double-buffered bf16 K/V tiles, FA2-style register softmax.
// smem per stage: KH,KL,VH,VL each 64 rows x 72 bf16 (144 B) = 9216 B.
// ---------------------------------------------------------------------------
#define ROWB 144                 // bytes per smem row (72 bf16)
#define ARRB (64 * ROWB)         // 9216 bytes per array
#define STAGEB (4 * ARRB)        // 36864 bytes per stage
#define ATTN_SMEM (2 * STAGEB)   // 73728

__device__ __forceinline__ void attn_issue_tile(char* smem, int st, int s0, int h,
                                                int tid) {
    char* sb = smem + st * STAGEB;
    const __nv_bfloat16* srcs[4] = {g_kh, g_kl, g_vh, g_vl};
#pragma unroll
    for (int i = 0; i < 8; i++) {
        int chunk = tid + i * 256;       // 0..2047
        int arr = chunk >> 9;            // 0..3
        int c = chunk & 511;
        int row = c >> 3;                // 0..63
        int c8 = c & 7;                  // 16-byte chunk within row
        const __nv_bfloat16* src = srcs[arr] +
            (size_t)(s0 + row) * D_MODEL + h * C_HEAD + c8 * 8;
        uint32_t dst = smem_u32(sb + arr * ARRB + row * ROWB + c8 * 16);
        cpa16(dst, src);
    }
}

__global__ void __launch_bounds__(256, 1)
attn_mma_kernel(float* __restrict__ out) {
    extern __shared__ char smem[];

    int tid = threadIdx.x;
    int lane = tid & 31;
    int warp = tid >> 5;
    int g = lane >> 2;
    int tg = lane & 3;
    int li = lane & 15;
    int h = blockIdx.y;
    int t0 = (int)(gridDim.x - 1 - blockIdx.x) * 128;  // big workloads first
    int rg = t0 + warp * 16 + g;
    int rg8 = rg + 8;

    // --- Q fragments from precomputed hi/lo bf16 (scale pre-applied) ---
    uint32_t qh[4][4], ql[4][4];
#pragma unroll
    for (int ks = 0; ks < 4; ks++) {
        int c0 = h * C_HEAD + ks * 16 + 2 * tg;
#pragma unroll
        for (int ai = 0; ai < 4; ai++) {
            int r = (ai & 1) ? rg8 : rg;
            int c = c0 + ((ai & 2) ? 8 : 0);
            qh[ks][ai] = *(const uint32_t*)&g_qh[(size_t)r * D_MODEL + c];
            ql[ks][ai] = *(const uint32_t*)&g_ql[(size_t)r * D_MODEL + c];
        }
    }

    float O[8][4];
#pragma unroll
    for (int nt = 0; nt < 8; nt++)
#pragma unroll
        for (int j = 0; j < 4; j++) O[nt][j] = 0.f;
    float m0r = -1e30f, m1r = -1e30f, l0r = 0.f, l1r = 0.f;

    int smax = t0 + 64;     // last key-tile start (rows up to t0+127)

    attn_issue_tile(smem, 0, 0, h, tid);
    cpa_commit();

    int it = 0;
    for (int s0 = 0; s0 <= smax; s0 += 64, it++) {
        int cur = it & 1;
        if (s0 + 64 <= smax) {
            attn_issue_tile(smem, cur ^ 1, s0 + 64, h, tid);
            cpa_commit();
            cpa_wait<1>();
        } else {
            cpa_wait<0>();
        }
        __syncthreads();

        char* sb = smem + cur * STAGEB;
        uint32_t baseKH = smem_u32(sb + (li & 7) * ROWB + ((li & 8) ? 16 : 0));
        uint32_t baseKL = baseKH + ARRB;
        uint32_t baseVH = smem_u32(sb + 2 * ARRB + li * ROWB);
        uint32_t baseVL = baseVH + ARRB;

        // --- S = (Q/8) @ K^T ---
        float sc[8][4];
#pragma unroll
        for (int nt = 0; nt < 8; nt++)
#pragma unroll
            for (int j = 0; j < 4; j++) sc[nt][j] = 0.f;

#pragma unroll
        for (int ks = 0; ks < 4; ks++) {
#pragma unroll
            for (int nt = 0; nt < 8; nt++) {
                uint32_t off = (uint32_t)(nt * 8 * ROWB + ks * 32);
                uint32_t bh0, bh1, bl0, bl1;
                ldm_x2(bh0, bh1, baseKH + off);
                ldm_x2(bl0, bl1, baseKL + off);
                mma_bf16_16x8x16(sc[nt], qh[ks], bh0, bh1);
                mma_bf16_16x8x16(sc[nt], qh[ks], bl0, bl1);
                mma_bf16_16x8x16(sc[nt], ql[ks], bh0, bh1);
            }
        }

        // --- causal mask (tiles that can cross the diagonal for this warp) ---
        if (s0 + 63 > rg) {
#pragma unroll
            for (int nt = 0; nt < 8; nt++) {
                int col = s0 + nt * 8 + 2 * tg;
                if (col > rg)      sc[nt][0] = -1e30f;
                if (col + 1 > rg)  sc[nt][1] = -1e30f;
                if (col > rg8)     sc[nt][2] = -1e30f;
                if (col + 1 > rg8) sc[nt][3] = -1e30f;
            }
        }

        // --- online softmax (rows rg and rg8) ---
        float mx0 = m0r, mx1 = m1r;
#pragma unroll
        for (int nt = 0; nt < 8; nt++) {
            mx0 = fmaxf(mx0, fmaxf(sc[nt][0], sc[nt][1]));
            mx1 = fmaxf(mx1, fmaxf(sc[nt][2], sc[nt][3]));
        }
        mx0 = fmaxf(mx0, __shfl_xor_sync(0xffffffffu, mx0, 1));
        mx0 = fmaxf(mx0, __shfl_xor_sync(0xffffffffu, mx0, 2));
        mx1 = fmaxf(mx1, __shfl_xor_sync(0xffffffffu, mx1, 1));
        mx1 = fmaxf(mx1, __shfl_xor_sync(0xffffffffu, mx1, 2));

        float sum0 = 0.f, sum1 = 0.f;
#pragma unroll
        for (int nt = 0; nt < 8; nt++) {
            sc[nt][0] = __expf(sc[nt][0] - mx0);
            sc[nt][1] = __expf(sc[nt][1] - mx0);
            sc[nt][2] = __expf(sc[nt][2] - mx1);
            sc[nt][3] = __expf(sc[nt][3] - mx1);
            sum0 += sc[nt][0] + sc[nt][1];
            sum1 += sc[nt][2] + sc[nt][3];
        }
        sum0 += __shfl_xor_sync(0xffffffffu, sum0, 1);
        sum0 += __shfl_xor_sync(0xffffffffu, sum0, 2);
        sum1 += __shfl_xor_sync(0xffffffffu, sum1, 1);
        sum1 += __shfl_xor_sync(0xffffffffu, sum1, 2);

        float corr0 = __expf(m0r - mx0);
        float corr1 = __expf(m1r - mx1);
        l0r = l0r * corr0 + sum0;
        l1r = l1r * corr1 + sum1;
        m0r = mx0;
        m1r = mx1;
#pragma unroll
        for (int nt = 0; nt < 8; nt++) {
            O[nt][0] *= corr0;
            O[nt][1] *= corr0;
            O[nt][2] *= corr1;
            O[nt][3] *= corr1;
        }

        // --- P fragments (hi/lo) from C-frag layout ---
        uint32_t ph[4][4], pl[4][4];
#pragma unroll
        for (int ks = 0; ks < 4; ks++) {
#pragma unroll
            for (int half = 0; half < 2; half++) {
                int nt = 2 * ks + half;
                float p0 = sc[nt][0], p1 = sc[nt][1];
                float p2 = sc[nt][2], p3 = sc[nt][3];
                __nv_bfloat16 h0 = __float2bfloat16(p0), h1 = __float2bfloat16(p1);
                __nv_bfloat16 h2 = __float2bfloat16(p2), h3 = __float2bfloat16(p3);
                ph[ks][0 + 2 * half] = pack_bf16(__bfloat162float(h0), __bfloat162float(h1));
                ph[ks][1 + 2 * half] = pack_bf16(__bfloat162float(h2), __bfloat162float(h3));
                pl[ks][0 + 2 * half] = pack_bf16(p0 - __bfloat162float(h0),
                                                 p1 - __bfloat162float(h1));
                pl[ks][1 + 2 * half] = pack_bf16(p2 - __bfloat162float(h2),
                                                 p3 - __bfloat162float(h3));
            }
        }

        // --- O += P @ V ---
#pragma unroll
        for (int ks = 0; ks < 4; ks++) {
#pragma unroll
            for (int nt = 0; nt < 8; nt++) {
                uint32_t off = (uint32_t)(ks * 16 * ROWB + nt * 16);
                uint32_t bh0, bh1, bl0, bl1;
                ldm_x2_trans(bh0, bh1, baseVH + off);
                ldm_x2_trans(bl0, bl1, baseVL + off);
                mma_bf16_16x8x16(O[nt], ph[ks], bh0, bh1);
                mma_bf16_16x8x16(O[nt], ph[ks], bl0, bl1);
                mma_bf16_16x8x16(O[nt], pl[ks], bh0, bh1);
            }
        }
        __syncthreads();
    }

    // --- normalize + write ---
    float inv0 = 1.f / l0r;
    float inv1 = 1.f / l1r;
#pragma unroll
    for (int nt = 0; nt < 8; nt++) {
        int cb = h * C_HEAD + nt * 8 + 2 * tg;
        *(float2*)&out[(size_t)rg * D_MODEL + cb] =
            make_float2(O[nt][0] * inv0, O[nt][1] * inv0);
        *(float2*)&out[(size_t)rg8 * D_MODEL + cb] =
            make_float2(O[nt][2] * inv1, O[nt][3] * inv1);
    }
}

// ---------------------------------------------------------------------------
extern "C" void kernel_launch(void* const* d_in, const int* in_sizes, int n_in,
                              void* d_out, int out_size) {
    const float* x      = (const float*)d_in[0];   // [4096,1024]
    const float* W_qkv  = (const float*)d_in[1];   // [3072,1024]
    const float* W_proj = (const float*)d_in[2];   // [1024,1024]
    float* out = (float*)d_out;                    // [4096,1024]

    float* qkv_ptr;
    float* attn_ptr;
    cudaGetSymbolAddress((void**)&qkv_ptr, g_qkv);
    cudaGetSymbolAddress((void**)&attn_ptr, g_attn);

    cudaFuncSetAttribute(attn_mma_kernel, cudaFuncAttributeMaxDynamicSharedMemorySize,
                         ATTN_SMEM);

    // 1) qkv = x @ W_qkv^T   (tensor-core split-bf16)
    {
        dim3 grid(QKV_W / BNg, T_SEQ / BMg);
        gemm_nt_bf16x3_kernel<<<grid, 256>>>(x, W_qkv, qkv_ptr, T_SEQ, QKV_W, D_MODEL);
    }

    // 2) fused RoPE + hi/lo bf16 precompute
    {
        int total = T_SEQ * N_HEAD * (C_HEAD / 2);   // 2097152
        rope_convert_kernel<<<total / 256, 256>>>(qkv_ptr);
    }

    // 3) causal attention (tensor-core, cp.async pipelined)
    {
        dim3 grid(T_SEQ / 128, N_HEAD);
        attn_mma_kernel<<<grid, 256, ATTN_SMEM>>>(attn_ptr);
    }

    // 4) out = attn @ W_proj^T   (tensor-core split-bf16)
    {
        dim3 grid(D_MODEL / BNg, T_SEQ / BMg);
        gemm_nt_bf16x3_kernel<<<grid, 256>>>(attn_ptr, W_proj, out, T_SEQ, D_MODEL, D_MODEL);
    }
}

// round 10
// speedup vs baseline: 1.9858x; 1.1140x over previous
#include <cuda_runtime.h>
#include <cuda_bf16.h>
#include <math.h>
#include <stdint.h>

#define T_SEQ 4096
#define D_MODEL 1024
#define N_HEAD 16
#define C_HEAD 64
#define QKV_W 3072

// Scratch (device globals: allocation-guard safe)
__device__ float g_qkv[(size_t)T_SEQ * QKV_W];     // [T][3D], q|k|v sections
__device__ float g_attn[(size_t)T_SEQ * D_MODEL];  // [T][D] attention output
// Precomputed hi/lo bf16 (RoPE'd; Q pre-scaled by 1/8)
__device__ __nv_bfloat16 g_qh[(size_t)T_SEQ * D_MODEL];
__device__ __nv_bfloat16 g_ql[(size_t)T_SEQ * D_MODEL];
__device__ __nv_bfloat16 g_kh[(size_t)T_SEQ * D_MODEL];
__device__ __nv_bfloat16 g_kl[(size_t)T_SEQ * D_MODEL];
__device__ __nv_bfloat16 g_vh[(size_t)T_SEQ * D_MODEL];
__device__ __nv_bfloat16 g_vl[(size_t)T_SEQ * D_MODEL];

// ---------------------------------------------------------------------------
// Common helpers
// ---------------------------------------------------------------------------
__device__ __forceinline__ uint32_t smem_u32(const void* p) {
    return (uint32_t)__cvta_generic_to_shared(p);
}

__device__ __forceinline__ uint32_t pack_bf16(float x, float y) {
    __nv_bfloat162 t = __floats2bfloat162_rn(x, y);
    return *(uint32_t*)&t;
}

__device__ __forceinline__ void mma_bf16_16x8x8(float* c,
                                                uint32_t a0, uint32_t a1,
                                                uint32_t b0) {
    asm volatile(
        "mma.sync.aligned.m16n8k8.row.col.f32.bf16.bf16.f32 "
        "{%0,%1,%2,%3}, {%4,%5}, {%6}, {%0,%1,%2,%3};"
        : "+f"(c[0]), "+f"(c[1]), "+f"(c[2]), "+f"(c[3])
        : "r"(a0), "r"(a1), "r"(b0));
}

__device__ __forceinline__ void mma_bf16_16x8x16(float* c, const uint32_t* a,
                                                 uint32_t b0, uint32_t b1) {
    asm volatile(
        "mma.sync.aligned.m16n8k16.row.col.f32.bf16.bf16.f32 "
        "{%0,%1,%2,%3}, {%4,%5,%6,%7}, {%8,%9}, {%0,%1,%2,%3};"
        : "+f"(c[0]), "+f"(c[1]), "+f"(c[2]), "+f"(c[3])
        : "r"(a[0]), "r"(a[1]), "r"(a[2]), "r"(a[3]), "r"(b0), "r"(b1));
}

__device__ __forceinline__ void ldm_x2(uint32_t& r0, uint32_t& r1, uint32_t addr) {
    asm volatile("ldmatrix.sync.aligned.m8n8.x2.shared.b16 {%0,%1}, [%2];"
                 : "=r"(r0), "=r"(r1) : "r"(addr));
}

__device__ __forceinline__ void ldm_x2_trans(uint32_t& r0, uint32_t& r1, uint32_t addr) {
    asm volatile("ldmatrix.sync.aligned.m8n8.x2.trans.shared.b16 {%0,%1}, [%2];"
                 : "=r"(r0), "=r"(r1) : "r"(addr));
}

__device__ __forceinline__ void cpa16(uint32_t dst, const __nv_bfloat16* src) {
    asm volatile("cp.async.cg.shared.global [%0], [%1], 16;"
                 :: "r"(dst), "l"(__cvta_generic_to_global(src)));
}
__device__ __forceinline__ void cpa_commit() {
    asm volatile("cp.async.commit_group;");
}
template <int N>
__device__ __forceinline__ void cpa_wait() {
    asm volatile("cp.async.wait_group %0;" :: "n"(N));
}

// ---------------------------------------------------------------------------
// Split-bf16 tensor-core NT GEMM. Same structure as R5/R6/R9 passing kernel;
// only change: __launch_bounds__(256, 2) for 2 CTAs/SM.
// ---------------------------------------------------------------------------
#define BMg 128
#define BNg 128
#define BKg 32

__global__ void __launch_bounds__(256, 2)
gemm_nt_bf16x3_kernel(const float* __restrict__ A,
                      const float* __restrict__ B,
                      float* __restrict__ C,
                      int M, int N, int K) {
    __shared__ __nv_bfloat16 Ah[BMg][BKg + 2];
    __shared__ __nv_bfloat16 Al[BMg][BKg + 2];
    __shared__ __nv_bfloat16 Bh[BNg][BKg + 2];
    __shared__ __nv_bfloat16 Bl[BNg][BKg + 2];

    int tid = threadIdx.x;
    int warp = tid >> 5;
    int lane = tid & 31;
    int wm = warp >> 2;
    int wn = warp & 3;
    int g = lane >> 2;
    int tg = lane & 3;
    int m0 = blockIdx.y * BMg;
    int n0 = blockIdx.x * BNg;
    int wm0 = wm * 64;
    int wn0 = wn * 32;

    float acc[4][4][4] = {};

    for (int k0 = 0; k0 < K; k0 += BKg) {
#pragma unroll
        for (int i = 0; i < 4; i++) {
            int f = tid + i * 256;
            int r = f >> 3;
            int c = (f & 7) * 4;
            float4 va = *(const float4*)(A + (size_t)(m0 + r) * K + k0 + c);
            float xs[4] = {va.x, va.y, va.z, va.w};
#pragma unroll
            for (int j = 0; j < 4; j++) {
                __nv_bfloat16 hh = __float2bfloat16(xs[j]);
                Ah[r][c + j] = hh;
                Al[r][c + j] = __float2bfloat16(xs[j] - __bfloat162float(hh));
            }
            float4 vb = *(const float4*)(B + (size_t)(n0 + r) * K + k0 + c);
            float ys[4] = {vb.x, vb.y, vb.z, vb.w};
#pragma unroll
            for (int j = 0; j < 4; j++) {
                __nv_bfloat16 hh = __float2bfloat16(ys[j]);
                Bh[r][c + j] = hh;
                Bl[r][c + j] = __float2bfloat16(ys[j] - __bfloat162float(hh));
            }
        }
        __syncthreads();

#pragma unroll
        for (int kc = 0; kc < BKg; kc += 8) {
            uint32_t ah[4][2], al[4][2], bh[4], bl[4];
#pragma unroll
            for (int mt = 0; mt < 4; mt++) {
                int r = wm0 + mt * 16 + g;
                ah[mt][0] = *(const uint32_t*)&Ah[r][kc + tg * 2];
                ah[mt][1] = *(const uint32_t*)&Ah[r + 8][kc + tg * 2];
                al[mt][0] = *(const uint32_t*)&Al[r][kc + tg * 2];
                al[mt][1] = *(const uint32_t*)&Al[r + 8][kc + tg * 2];
            }
#pragma unroll
            for (int nt = 0; nt < 4; nt++) {
                int r = wn0 + nt * 8 + g;
                bh[nt] = *(const uint32_t*)&Bh[r][kc + tg * 2];
                bl[nt] = *(const uint32_t*)&Bl[r][kc + tg * 2];
            }
#pragma unroll
            for (int mt = 0; mt < 4; mt++) {
#pragma unroll
                for (int nt = 0; nt < 4; nt++) {
                    mma_bf16_16x8x8(acc[mt][nt], ah[mt][0], ah[mt][1], bh[nt]);
                    mma_bf16_16x8x8(acc[mt][nt], ah[mt][0], ah[mt][1], bl[nt]);
                    mma_bf16_16x8x8(acc[mt][nt], al[mt][0], al[mt][1], bh[nt]);
                }
            }
        }
        __syncthreads();
    }

#pragma unroll
    for (int mt = 0; mt < 4; mt++) {
        int r = m0 + wm0 + mt * 16 + g;
#pragma unroll
        for (int nt = 0; nt < 4; nt++) {
            int cb = n0 + wn0 + nt * 8 + tg * 2;
            *(float2*)&C[(size_t)r * N + cb] =
                make_float2(acc[mt][nt][0], acc[mt][nt][1]);
            *(float2*)&C[(size_t)(r + 8) * N + cb] =
                make_float2(acc[mt][nt][2], acc[mt][nt][3]);
        }
    }
}

// ---------------------------------------------------------------------------
// Fused RoPE + hi/lo bf16 conversion (unchanged).
// ---------------------------------------------------------------------------
__global__ void rope_convert_kernel(const float* __restrict__ qkv) {
    int idx = blockIdx.x * blockDim.x + threadIdx.x;   // 0 .. T*512-1
    int p = idx & 31;                // pair index within head
    int h = (idx >> 5) & 15;
    int t = idx >> 9;
    if (t >= T_SEQ) return;

    const float LOG_10000 = 9.210340371976184f;
    float inv_freq = expf(-(2.f * (float)p / (float)C_HEAD) * LOG_10000);
    float ang = (float)t * inv_freq;
    float s, c;
    sincosf(ang, &s, &c);

    int d = h * C_HEAD + 2 * p;
    size_t qbase = (size_t)t * QKV_W + d;
    size_t obase = (size_t)t * D_MODEL + d;

    // q: rope + scale + split
    {
        float x1 = qkv[qbase], x2 = qkv[qbase + 1];
        float r1 = (x1 * c - x2 * s) * 0.125f;
        float r2 = (x2 * c + x1 * s) * 0.125f;
        __nv_bfloat16 h1 = __float2bfloat16(r1), h2 = __float2bfloat16(r2);
        *(__nv_bfloat162*)&g_qh[obase] = __nv_bfloat162(h1, h2);
        *(__nv_bfloat162*)&g_ql[obase] = __nv_bfloat162(
            __float2bfloat16(r1 - __bfloat162float(h1)),
            __float2bfloat16(r2 - __bfloat162float(h2)));
    }
    // k: rope + split
    {
        float x1 = qkv[qbase + D_MODEL], x2 = qkv[qbase + D_MODEL + 1];
        float r1 = x1 * c - x2 * s;
        float r2 = x2 * c + x1 * s;
        __nv_bfloat16 h1 = __float2bfloat16(r1), h2 = __float2bfloat16(r2);
        *(__nv_bfloat162*)&g_kh[obase] = __nv_bfloat162(h1, h2);
        *(__nv_bfloat162*)&g_kl[obase] = __nv_bfloat162(
            __float2bfloat16(r1 - __bfloat162float(h1)),
            __float2bfloat16(r2 - __bfloat162float(h2)));
    }
    // v: split
    {
        float x1 = qkv[qbase + 2 * D_MODEL], x2 = qkv[qbase + 2 * D_MODEL + 1];
        __nv_bfloat16 h1 = __float2bfloat16(x1), h2 = __float2bfloat16(x2);
        *(__nv_bfloat162*)&g_vh[obase] = __nv_bfloat162(h1, h2);
        *(__nv_bfloat162*)&g_vl[obase] = __nv_bfloat162(
            __float2bfloat16(x1 - __bfloat162float(h1)),
            __float2bfloat16(x2 - __bfloat162float(h2)));
    }
}

// ---------------------------------------------------------------------------
// Tensor-core flash attention, Br=128, Bc=64, 256 threads (8 warps),
// cp.async double-buffered bf16 K/V tiles, FA2-style register softmax.
// Changes from R9: P hi/lo computed inline per ks (reg reduction),
// __launch_bounds__(256, 2) for cross-CTA phase overlap.
// ---------------------------------------------------------------------------
#define ROWB 144                 // bytes per smem row (72 bf16)
#define ARRB (64 * ROWB)         // 9216 bytes per array
#define STAGEB (4 * ARRB)        // 36864 bytes per stage
#define ATTN_SMEM (2 * STAGEB)   // 73728

__device__ __forceinline__ void attn_issue_tile(char* smem, int st, int s0, int h,
                                                int tid) {
    char* sb = smem + st * STAGEB;
    const __nv_bfloat16* srcs[4] = {g_kh, g_kl, g_vh, g_vl};
#pragma unroll
    for (int i = 0; i < 8; i++) {
        int chunk = tid + i * 256;       // 0..2047
        int arr = chunk >> 9;            // 0..3
        int c = chunk & 511;
        int row = c >> 3;                // 0..63
        int c8 = c & 7;                  // 16-byte chunk within row
        const __nv_bfloat16* src = srcs[arr] +
            (size_t)(s0 + row) * D_MODEL + h * C_HEAD + c8 * 8;
        uint32_t dst = smem_u32(sb + arr * ARRB + row * ROWB + c8 * 16);
        cpa16(dst, src);
    }
}

__global__ void __launch_bounds__(256, 2)
attn_mma_kernel(float* __restrict__ out) {
    extern __shared__ char smem[];

    int tid = threadIdx.x;
    int lane = tid & 31;
    int warp = tid >> 5;
    int g = lane >> 2;
    int tg = lane & 3;
    int li = lane & 15;
    int h = blockIdx.y;
    int t0 = (int)(gridDim.x - 1 - blockIdx.x) * 128;  // big workloads first
    int rg = t0 + warp * 16 + g;
    int rg8 = rg + 8;

    // --- Q fragments from precomputed hi/lo bf16 (scale pre-applied) ---
    uint32_t qh[4][4], ql[4][4];
#pragma unroll
    for (int ks = 0; ks < 4; ks++) {
        int c0 = h * C_HEAD + ks * 16 + 2 * tg;
#pragma unroll
        for (int ai = 0; ai < 4; ai++) {
            int r = (ai & 1) ? rg8 : rg;
            int c = c0 + ((ai & 2) ? 8 : 0);
            qh[ks][ai] = *(const uint32_t*)&g_qh[(size_t)r * D_MODEL + c];
            ql[ks][ai] = *(const uint32_t*)&g_ql[(size_t)r * D_MODEL + c];
        }
    }

    float O[8][4];
#pragma unroll
    for (int nt = 0; nt < 8; nt++)
#pragma unroll
        for (int j = 0; j < 4; j++) O[nt][j] = 0.f;
    float m0r = -1e30f, m1r = -1e30f, l0r = 0.f, l1r = 0.f;

    int smax = t0 + 64;     // last key-tile start (rows up to t0+127)

    attn_issue_tile(smem, 0, 0, h, tid);
    cpa_commit();

    int it = 0;
    for (int s0 = 0; s0 <= smax; s0 += 64, it++) {
        int cur = it & 1;
        if (s0 + 64 <= smax) {
            attn_issue_tile(smem, cur ^ 1, s0 + 64, h, tid);
            cpa_commit();
            cpa_wait<1>();
        } else {
            cpa_wait<0>();
        }
        __syncthreads();

        char* sb = smem + cur * STAGEB;
        uint32_t baseKH = smem_u32(sb + (li & 7) * ROWB + ((li & 8) ? 16 : 0));
        uint32_t baseKL = baseKH + ARRB;
        uint32_t baseVH = smem_u32(sb + 2 * ARRB + li * ROWB);
        uint32_t baseVL = baseVH + ARRB;

        // --- S = (Q/8) @ K^T ---
        float sc[8][4];
#pragma unroll
        for (int nt = 0; nt < 8; nt++)
#pragma unroll
            for (int j = 0; j < 4; j++) sc[nt][j] = 0.f;

#pragma unroll
        for (int ks = 0; ks < 4; ks++) {
#pragma unroll
            for (int nt = 0; nt < 8; nt++) {
                uint32_t off = (uint32_t)(nt * 8 * ROWB + ks * 32);
                uint32_t bh0, bh1, bl0, bl1;
                ldm_x2(bh0, bh1, baseKH + off);
                ldm_x2(bl0, bl1, baseKL + off);
                mma_bf16_16x8x16(sc[nt], qh[ks], bh0, bh1);
                mma_bf16_16x8x16(sc[nt], qh[ks], bl0, bl1);
                mma_bf16_16x8x16(sc[nt], ql[ks], bh0, bh1);
            }
        }

        // --- causal mask (tiles that can cross the diagonal for this warp) ---
        if (s0 + 63 > rg) {
#pragma unroll
            for (int nt = 0; nt < 8; nt++) {
                int col = s0 + nt * 8 + 2 * tg;
                if (col > rg)      sc[nt][0] = -1e30f;
                if (col + 1 > rg)  sc[nt][1] = -1e30f;
                if (col > rg8)     sc[nt][2] = -1e30f;
                if (col + 1 > rg8) sc[nt][3] = -1e30f;
            }
        }

        // --- online softmax (rows rg and rg8) ---
        float mx0 = m0r, mx1 = m1r;
#pragma unroll
        for (int nt = 0; nt < 8; nt++) {
            mx0 = fmaxf(mx0, fmaxf(sc[nt][0], sc[nt][1]));
            mx1 = fmaxf(mx1, fmaxf(sc[nt][2], sc[nt][3]));
        }
        mx0 = fmaxf(mx0, __shfl_xor_sync(0xffffffffu, mx0, 1));
        mx0 = fmaxf(mx0, __shfl_xor_sync(0xffffffffu, mx0, 2));
        mx1 = fmaxf(mx1, __shfl_xor_sync(0xffffffffu, mx1, 1));
        mx1 = fmaxf(mx1, __shfl_xor_sync(0xffffffffu, mx1, 2));

        float sum0 = 0.f, sum1 = 0.f;
#pragma unroll
        for (int nt = 0; nt < 8; nt++) {
            sc[nt][0] = __expf(sc[nt][0] - mx0);
            sc[nt][1] = __expf(sc[nt][1] - mx0);
            sc[nt][2] = __expf(sc[nt][2] - mx1);
            sc[nt][3] = __expf(sc[nt][3] - mx1);
            sum0 += sc[nt][0] + sc[nt][1];
            sum1 += sc[nt][2] + sc[nt][3];
        }
        sum0 += __shfl_xor_sync(0xffffffffu, sum0, 1);
        sum0 += __shfl_xor_sync(0xffffffffu, sum0, 2);
        sum1 += __shfl_xor_sync(0xffffffffu, sum1, 1);
        sum1 += __shfl_xor_sync(0xffffffffu, sum1, 2);

        float corr0 = __expf(m0r - mx0);
        float corr1 = __expf(m1r - mx1);
        l0r = l0r * corr0 + sum0;
        l1r = l1r * corr1 + sum1;
        m0r = mx0;
        m1r = mx1;
#pragma unroll
        for (int nt = 0; nt < 8; nt++) {
            O[nt][0] *= corr0;
            O[nt][1] *= corr0;
            O[nt][2] *= corr1;
            O[nt][3] *= corr1;
        }

        // --- O += P @ V, P hi/lo fragments computed inline per ks ---
#pragma unroll
        for (int ks = 0; ks < 4; ks++) {
            uint32_t ph[4], pl[4];
#pragma unroll
            for (int half = 0; half < 2; half++) {
                int nt = 2 * ks + half;
                float p0 = sc[nt][0], p1 = sc[nt][1];
                float p2 = sc[nt][2], p3 = sc[nt][3];
                __nv_bfloat16 h0 = __float2bfloat16(p0), h1 = __float2bfloat16(p1);
                __nv_bfloat16 h2 = __float2bfloat16(p2), h3 = __float2bfloat16(p3);
                ph[0 + 2 * half] = pack_bf16(__bfloat162float(h0), __bfloat162float(h1));
                ph[1 + 2 * half] = pack_bf16(__bfloat162float(h2), __bfloat162float(h3));
                pl[0 + 2 * half] = pack_bf16(p0 - __bfloat162float(h0),
                                             p1 - __bfloat162float(h1));
                pl[1 + 2 * half] = pack_bf16(p2 - __bfloat162float(h2),
                                             p3 - __bfloat162float(h3));
            }
#pragma unroll
            for (int nt = 0; nt < 8; nt++) {
                uint32_t off = (uint32_t)(ks * 16 * ROWB + nt * 16);
                uint32_t bh0, bh1, bl0, bl1;
                ldm_x2_trans(bh0, bh1, baseVH + off);
                ldm_x2_trans(bl0, bl1, baseVL + off);
                mma_bf16_16x8x16(O[nt], ph, bh0, bh1);
                mma_bf16_16x8x16(O[nt], ph, bl0, bl1);
                mma_bf16_16x8x16(O[nt], pl, bh0, bh1);
            }
        }
        __syncthreads();
    }

    // --- normalize + write ---
    float inv0 = 1.f / l0r;
    float inv1 = 1.f / l1r;
#pragma unroll
    for (int nt = 0; nt < 8; nt++) {
        int cb = h * C_HEAD + nt * 8 + 2 * tg;
        *(float2*)&out[(size_t)rg * D_MODEL + cb] =
            make_float2(O[nt][0] * inv0, O[nt][1] * inv0);
        *(float2*)&out[(size_t)rg8 * D_MODEL + cb] =
            make_float2(O[nt][2] * inv1, O[nt][3] * inv1);
    }
}

// ---------------------------------------------------------------------------
extern "C" void kernel_launch(void* const* d_in, const int* in_sizes, int n_in,
                              void* d_out, int out_size) {
    const float* x      = (const float*)d_in[0];   // [4096,1024]
    const float* W_qkv  = (const float*)d_in[1];   // [3072,1024]
    const float* W_proj = (const float*)d_in[2];   // [1024,1024]
    float* out = (float*)d_out;                    // [4096,1024]

    float* qkv_ptr;
    float* attn_ptr;
    cudaGetSymbolAddress((void**)&qkv_ptr, g_qkv);
    cudaGetSymbolAddress((void**)&attn_ptr, g_attn);

    cudaFuncSetAttribute(attn_mma_kernel, cudaFuncAttributeMaxDynamicSharedMemorySize,
                         ATTN_SMEM);

    // 1) qkv = x @ W_qkv^T   (tensor-core split-bf16)
    {
        dim3 grid(QKV_W / BNg, T_SEQ / BMg);
        gemm_nt_bf16x3_kernel<<<grid, 256>>>(x, W_qkv, qkv_ptr, T_SEQ, QKV_W, D_MODEL);
    }

    // 2) fused RoPE + hi/lo bf16 precompute
    {
        int total = T_SEQ * N_HEAD * (C_HEAD / 2);   // 2097152
        rope_convert_kernel<<<total / 256, 256>>>(qkv_ptr);
    }

    // 3) causal attention (tensor-core, cp.async pipelined)
    {
        dim3 grid(T_SEQ / 128, N_HEAD);
        attn_mma_kernel<<<grid, 256, ATTN_SMEM>>>(attn_ptr);
    }

    // 4) out = attn @ W_proj^T   (tensor-core split-bf16)
    {
        dim3 grid(D_MODEL / BNg, T_SEQ / BMg);
        gemm_nt_bf16x3_kernel<<<grid, 256>>>(attn_ptr, W_proj, out, T_SEQ, D_MODEL, D_MODEL);
    }
}